// round 6
// baseline (speedup 1.0000x reference)
#include <cuda_runtime.h>
#include <cuda_fp16.h>

#define GSZ 64
#define NTILE (GSZ * GSZ * GSZ)   // 262144 tiles

// All-origins tile buffer: tile (z, y0, x0) holds the 4x4 (y,x) patch of
// cells (z, y0..y0+3, x0..x0+3), 4 channels, fp16 -> 16 cells * 8B = 128B
// = one cache line. 32 MB (L2-resident).
// uint4 j (j=0..7) holds cells 2j, 2j+1 (cell index c = dy*4+dx).
// Cell = {half2(ch0,ch1), half2(ch2,ch3)}.
__device__ uint4 g_tiles[NTILE * 8];

// ---------------------------------------------------------------------------
// Prep: one thread per (tile, dy). Tiles with x0>60 or y0>60 are never read
// by k_main (base indices are clamped to [1,61] there), so we clamp only the
// READ base (keeps all loads in-bounds & contiguous) and skip per-cell clamps.
// ---------------------------------------------------------------------------
__global__ void __launch_bounds__(256) k_prep(const float* __restrict__ knots)
{
    int tid = blockIdx.x * 256 + threadIdx.x;     // NTILE*4 threads
    int t  = tid >> 2;
    int dy = tid & 3;
    if (t >= NTILE) return;

    int z  = t >> 12;
    int y0 = (t >> 6) & 63;
    int x0 = t & 63;
    int y  = min(y0, GSZ - 4) + dy;     // <= 63, in-bounds
    int xc = min(x0, GSZ - 4);          // xc+3 <= 63, contiguous 64B read

    const float4* src = reinterpret_cast<const float4*>(knots)
                      + (z * GSZ + y) * GSZ + xc;

    float4 k0 = __ldg(src + 0);
    float4 k1 = __ldg(src + 1);
    float4 k2 = __ldg(src + 2);
    float4 k3 = __ldg(src + 3);

    uint4 o0, o1;
    __half2 h;
    h = __floats2half2_rn(k0.x, k0.y); o0.x = *reinterpret_cast<unsigned*>(&h);
    h = __floats2half2_rn(k0.z, k0.w); o0.y = *reinterpret_cast<unsigned*>(&h);
    h = __floats2half2_rn(k1.x, k1.y); o0.z = *reinterpret_cast<unsigned*>(&h);
    h = __floats2half2_rn(k1.z, k1.w); o0.w = *reinterpret_cast<unsigned*>(&h);
    h = __floats2half2_rn(k2.x, k2.y); o1.x = *reinterpret_cast<unsigned*>(&h);
    h = __floats2half2_rn(k2.z, k2.w); o1.y = *reinterpret_cast<unsigned*>(&h);
    h = __floats2half2_rn(k3.x, k3.y); o1.z = *reinterpret_cast<unsigned*>(&h);
    h = __floats2half2_rn(k3.z, k3.w); o1.w = *reinterpret_cast<unsigned*>(&h);

    g_tiles[t * 8 + dy * 2 + 0] = o0;
    g_tiles[t * 8 + dy * 2 + 1] = o1;
}

// ---------------------------------------------------------------------------
// Main: quad mapping; lane lx owns y-row dy=lx. TWO points per quad for MLP:
// 8 independent LDG.256 in flight per lane, two independent fp16-dot chains.
// Per point per z: one 256-bit load (quad covers the 128B tile line in a
// single warp instruction -> 1 L1 wavefront per point per z).
// ---------------------------------------------------------------------------
__global__ void __launch_bounds__(256) k_main(const float* __restrict__ coords,
                                              float* __restrict__ out,
                                              int n)
{
    int tid = blockIdx.x * 256 + threadIdx.x;
    int qg = tid >> 2;       // global quad id
    int lx = tid & 3;        // y-tap of this lane
    int p0 = qg * 2;
    if (p0 >= n) return;
    bool have1 = (p0 + 1 < n);
    int pids[2] = {p0, have1 ? p0 + 1 : p0};

    const uint4* tb[2];
    float czv[2][4];
    float cylv[2];
    __half2 hx[2][4];

#pragma unroll
    for (int s = 0; s < 2; s++) {
        int p = pids[s];
        float zc = __ldg(&coords[p * 3 + 0]);
        float yc = __ldg(&coords[p * 3 + 1]);
        float xc = __ldg(&coords[p * 3 + 2]);

        float fz = floorf(zc), fy = floorf(yc), fx = floorf(xc);
        int iz = (int)fz, iy = (int)fy, ix = (int)fx;
        float sz = zc - fz, sy = yc - fy, sx = xc - fx;
        iz = min(max(iz, 1), GSZ - 3);
        iy = min(max(iy, 1), GSZ - 3);
        ix = min(max(ix, 1), GSZ - 3);

        czv[s][0] = sz * (-0.5f + sz * (1.0f - 0.5f * sz));
        czv[s][1] = 1.0f + sz * sz * (-2.5f + 1.5f * sz);
        czv[s][2] = sz * (0.5f + sz * (2.0f - 1.5f * sz));
        czv[s][3] = sz * sz * (0.5f * sz - 0.5f);

        {
            float c0 = sy * (-0.5f + sy * (1.0f - 0.5f * sy));
            float c1 = 1.0f + sy * sy * (-2.5f + 1.5f * sy);
            float c2 = sy * (0.5f + sy * (2.0f - 1.5f * sy));
            float c3 = sy * sy * (0.5f * sy - 0.5f);
            float ca = (lx & 1) ? c1 : c0;
            float cb = (lx & 1) ? c3 : c2;
            cylv[s] = (lx & 2) ? cb : ca;
        }
        {
            float c0 = sx * (-0.5f + sx * (1.0f - 0.5f * sx));
            float c1 = 1.0f + sx * sx * (-2.5f + 1.5f * sx);
            float c2 = sx * (0.5f + sx * (2.0f - 1.5f * sx));
            float c3 = sx * sx * (0.5f * sx - 0.5f);
            hx[s][0] = __float2half2_rn(c0);
            hx[s][1] = __float2half2_rn(c1);
            hx[s][2] = __float2half2_rn(c2);
            hx[s][3] = __float2half2_rn(c3);
        }

        tb[s] = g_tiles + (size_t)(((iz - 1) * GSZ + (iy - 1)) * GSZ + (ix - 1)) * 8
                        + lx * 2;
    }

    unsigned long long a01[2] = {0ull, 0ull};
    unsigned long long a23[2] = {0ull, 0ull};

#pragma unroll
    for (int zi = 0; zi < 4; zi++) {
#pragma unroll
        for (int s = 0; s < 2; s++) {
            const unsigned* tp = reinterpret_cast<const unsigned*>(
                tb[s] + (size_t)zi * (GSZ * GSZ * 8));

            unsigned r0, r1, r2, r3, r4, r5, r6, r7;
            asm("ld.global.nc.v8.b32 {%0,%1,%2,%3,%4,%5,%6,%7}, [%8];"
                : "=r"(r0), "=r"(r1), "=r"(r2), "=r"(r3),
                  "=r"(r4), "=r"(r5), "=r"(r6), "=r"(r7)
                : "l"(tp));

            __half2 c0_01 = *reinterpret_cast<__half2*>(&r0);
            __half2 c0_23 = *reinterpret_cast<__half2*>(&r1);
            __half2 c1_01 = *reinterpret_cast<__half2*>(&r2);
            __half2 c1_23 = *reinterpret_cast<__half2*>(&r3);
            __half2 c2_01 = *reinterpret_cast<__half2*>(&r4);
            __half2 c2_23 = *reinterpret_cast<__half2*>(&r5);
            __half2 c3_01 = *reinterpret_cast<__half2*>(&r6);
            __half2 c3_23 = *reinterpret_cast<__half2*>(&r7);

            __half2 d01 = __hmul2(hx[s][0], c0_01);
            d01 = __hfma2(hx[s][1], c1_01, d01);
            d01 = __hfma2(hx[s][2], c2_01, d01);
            d01 = __hfma2(hx[s][3], c3_01, d01);
            __half2 d23 = __hmul2(hx[s][0], c0_23);
            d23 = __hfma2(hx[s][1], c1_23, d23);
            d23 = __hfma2(hx[s][2], c2_23, d23);
            d23 = __hfma2(hx[s][3], c3_23, d23);

            float wz = czv[s][zi] * cylv[s];
            float2 f01 = __half22float2(d01);
            float2 f23 = __half22float2(d23);

            unsigned long long wz2, v01, v23;
            asm("mov.b64 %0, {%1, %1};" : "=l"(wz2) : "f"(wz));
            asm("mov.b64 %0, {%1, %2};" : "=l"(v01) : "f"(f01.x), "f"(f01.y));
            asm("mov.b64 %0, {%1, %2};" : "=l"(v23) : "f"(f23.x), "f"(f23.y));
            asm("fma.rn.f32x2 %0, %1, %2, %3;"
                : "=l"(a01[s]) : "l"(wz2), "l"(v01), "l"(a01[s]));
            asm("fma.rn.f32x2 %0, %1, %2, %3;"
                : "=l"(a23[s]) : "l"(wz2), "l"(v23), "l"(a23[s]));
        }
    }

#pragma unroll
    for (int s = 0; s < 2; s++) {
        float a0, a1, a2, a3;
        asm("mov.b64 {%0, %1}, %2;" : "=f"(a0), "=f"(a1) : "l"(a01[s]));
        asm("mov.b64 {%0, %1}, %2;" : "=f"(a2), "=f"(a3) : "l"(a23[s]));

#pragma unroll
        for (int d = 1; d < 4; d <<= 1) {
            a0 += __shfl_xor_sync(0xffffffffu, a0, d);
            a1 += __shfl_xor_sync(0xffffffffu, a1, d);
            a2 += __shfl_xor_sync(0xffffffffu, a2, d);
            a3 += __shfl_xor_sync(0xffffffffu, a3, d);
        }

        if (lx == 0 && (s == 0 || have1))
            reinterpret_cast<float4*>(out)[pids[s]] = make_float4(a0, a1, a2, a3);
    }
}

// ---------------------------------------------------------------------------
extern "C" void kernel_launch(void* const* d_in, const int* in_sizes, int n_in,
                              void* d_out, int out_size) {
    const float* coords = (const float*)d_in[0];  // [N,3] f32
    const float* knots  = (const float*)d_in[1];  // [64,64,64,4] f32
    float* out          = (float*)d_out;          // [N,4] f32

    int n = in_sizes[0] / 3;

    int prep_threads = NTILE * 4;
    k_prep<<<(prep_threads + 255) / 256, 256>>>(knots);

    long long quads = (n + 1) / 2;          // 2 points per quad
    long long total = 4LL * quads;          // lanes
    k_main<<<(int)((total + 255) / 256), 256>>>(coords, out, n);
}